// round 14
// baseline (speedup 1.0000x reference)
#include <cuda_runtime.h>

// Problem constants (fixed shapes per reference)
#define KROWS 1025
#define F     8192
#define NCHUNK 128
#define ROWS_PER_CHUNK 8   // 1024/128

// Device scratch (no allocations in kernel_launch)
__device__ float g_partial[NCHUNK * F];   // 4 MB
__device__ float g_scale[F];

// Kernel 1: partial |x| column sums over rows 1..1024.
// 8 col-groups x 128 row-chunks = 1024 blocks (R7-proven configuration).
__global__ void __launch_bounds__(256) relu_z_partial_abs(
    const float* __restrict__ x)
{
    int c4    = (blockIdx.x << 8) + threadIdx.x;   // 0..F/4-1
    int chunk = blockIdx.y;                        // 0..127
    int r0 = 1 + chunk * ROWS_PER_CHUNK;

    const float4* p = (const float4*)(x + (size_t)r0 * F) + c4;
    float4 s = make_float4(0.f, 0.f, 0.f, 0.f);
    #pragma unroll
    for (int r = 0; r < ROWS_PER_CHUNK; ++r) {
        float4 v = p[(size_t)r * (F / 4)];
        s.x += fabsf(v.x);
        s.y += fabsf(v.y);
        s.z += fabsf(v.z);
        s.w += fabsf(v.w);
    }
    ((float4*)(g_partial + chunk * F))[c4] = s;
}

// Kernel 2: fold the 128 partials (L2-resident, plain loads — R7 config)
// -> scale; write center row + ext diagonal float4. 32 blocks x 256 threads.
__global__ void __launch_bounds__(256) relu_z_finalize(
    const float* __restrict__ x,
    const float* __restrict__ lambdas,
    float* __restrict__ out)
{
    int f = blockIdx.x * blockDim.x + threadIdx.x;   // 0..F-1
    float abssum = 0.0f;
    #pragma unroll 16
    for (int c = 0; c < NCHUNK; ++c) abssum += g_partial[c * F + f];

    float ctr = x[f];                 // x[0][f]
    float l = ctr - abssum;
    float u = ctr + abssum;
    float lam = lambdas[f];

    float pos   = (l > 0.0f) ? 1.0f : 0.0f;
    float cross = ((u > 0.0f) && (l < 0.0f)) ? 1.0f : 0.0f;
    float d     = fmaxf(-l * lam, u * (1.0f - lam));
    float scale = pos + cross * lam;
    float half  = 0.5f * cross * d;

    g_scale[f] = scale;
    out[f] = scale * ctr + half;      // center row

    // diagonal float4 of the ext block (store_all skips this slot)
    float4 dv = make_float4(0.f, 0.f, 0.f, 0.f);
    ((float*)&dv)[f & 3] = half;
    ((float4*)(out + (size_t)(KROWS + f) * F))[f >> 2] = dv;
}

// Kernel 3: ALL remaining stores in one launch, FULL-ROW units.
// 256 threads x 8 float4 = 2048 float4 = one row per block.
//   blocks [0, 1024)    : body rows 1..1024, out = scale * x (x is L2-hot)
//   blocks [1024, 9216) : ext rows, streaming zeros, skip diagonal float4
__global__ void __launch_bounds__(256) relu_z_store_all(
    const float* __restrict__ x, float* __restrict__ out)
{
    const int b   = blockIdx.x;
    const int tid = threadIdx.x;

    if (b < 1024) {
        int r = 1 + b;
        const float4* xs = (const float4*)(x + (size_t)r * F);
        const float4* sc = (const float4*)g_scale;
        float4* os = (float4*)(out + (size_t)r * F);
        #pragma unroll
        for (int j = 0; j < 8; ++j) {
            int i = tid + (j << 8);
            float4 v = xs[i];
            float4 s = sc[i];
            float4 o;
            o.x = s.x * v.x;
            o.y = s.y * v.y;
            o.z = s.z * v.z;
            o.w = s.w * v.w;
            __stcs(&os[i], o);             // out never re-read: bypass L2 fill
        }
    } else {
        int row   = b - 1024;              // 0..8191
        int diag4 = row >> 2;              // float4 slot owned by finalize
        float4* os = (float4*)(out + (size_t)(KROWS + row) * F);
        const float4 z = make_float4(0.f, 0.f, 0.f, 0.f);

        // Thread tid writes slots tid + j*256; collision iff low 8 bits match.
        if ((diag4 & 255) != tid) {
            #pragma unroll
            for (int j = 0; j < 8; ++j) __stcs(&os[tid + (j << 8)], z);
        } else {
            #pragma unroll
            for (int j = 0; j < 8; ++j) {
                int i = tid + (j << 8);
                if (i != diag4) __stcs(&os[i], z);
            }
        }
    }
}

extern "C" void kernel_launch(void* const* d_in, const int* in_sizes, int n_in,
                              void* d_out, int out_size) {
    const float* x       = (const float*)d_in[0];
    const float* lambdas = (const float*)d_in[1];
    float* out           = (float*)d_out;

    // 1) Partial abs-sums: 8 col-groups x 128 row-chunks = 1024 blocks
    {
        dim3 grid(8, NCHUNK);
        relu_z_partial_abs<<<grid, 256>>>(x);
    }
    // 2) Finalize: scale, center row, ext diagonal (32 blocks)
    relu_z_finalize<<<F / 256, 256>>>(x, lambdas, out);
    // 3) Everything else: body rows + ext zeros, one launch, full-row units
    relu_z_store_all<<<1024 + 8192, 256>>>(x, out);
}

// round 15
// speedup vs baseline: 1.0287x; 1.0287x over previous
#include <cuda_runtime.h>

// Problem constants (fixed shapes per reference)
#define KROWS 1025
#define F     8192
#define NCHUNK 128
#define ROWS_PER_CHUNK 8   // 1024/128

// Device scratch (no allocations in kernel_launch)
__device__ float g_partial[NCHUNK * F];   // 4 MB
__device__ float g_scale[F];

// Kernel 1: partial column-wise sum of |x| over rows 1..1024.
// 8 col-blocks x 128 row-chunks = 1024 blocks, 262K threads.
__global__ void relu_z_partial_abs(const float* __restrict__ x) {
    int c4    = blockIdx.x * blockDim.x + threadIdx.x;  // 0..F/4-1
    int chunk = blockIdx.y;                             // 0..127
    int r0 = 1 + chunk * ROWS_PER_CHUNK;

    const float4* p = (const float4*)(x + (size_t)r0 * F) + c4;
    float4 s = make_float4(0.f, 0.f, 0.f, 0.f);
    #pragma unroll
    for (int r = 0; r < ROWS_PER_CHUNK; ++r) {
        float4 v = p[(size_t)r * (F / 4)];
        s.x += fabsf(v.x);
        s.y += fabsf(v.y);
        s.z += fabsf(v.z);
        s.w += fabsf(v.w);
    }
    ((float4*)(g_partial + chunk * F))[c4] = s;
}

// Kernel 2: fold partials -> scale; write center row + ext diagonal float4.
__global__ void relu_z_finalize(const float* __restrict__ x,
                                const float* __restrict__ lambdas,
                                float* __restrict__ out) {
    int f = blockIdx.x * blockDim.x + threadIdx.x;
    float abssum = 0.0f;
    #pragma unroll 16
    for (int c = 0; c < NCHUNK; ++c) abssum += g_partial[c * F + f];

    float ctr = x[f];                 // x[0][f]
    float l = ctr - abssum;
    float u = ctr + abssum;
    float lam = lambdas[f];

    float pos   = (l > 0.0f) ? 1.0f : 0.0f;
    float cross = ((u > 0.0f) && (l < 0.0f)) ? 1.0f : 0.0f;
    float d     = fmaxf(-l * lam, u * (1.0f - lam));
    float scale = pos + cross * lam;
    float half  = 0.5f * cross * d;

    g_scale[f] = scale;
    out[f] = scale * ctr + half;      // center row

    // diagonal float4 of the ext block (store_all skips this slot)
    float4 dv = make_float4(0.f, 0.f, 0.f, 0.f);
    ((float*)&dv)[f & 3] = half;
    ((float4*)(out + (size_t)(KROWS + f) * F))[f >> 2] = dv;
}

// Kernel 3: ALL remaining stores in one launch.
// Unit = half a row = 1024 float4 = 256 threads x 4 float4.
//   blocks [0, 2048)      : body rows 1..1024, out = scale * x (x is L2-hot)
//   blocks [2048, 18432)  : ext rows, streaming zeros, skip diagonal float4
// Body units have the lowest block indices -> first wave, maximizing L2 reuse.
__global__ void __launch_bounds__(256) relu_z_store_all(
    const float* __restrict__ x, float* __restrict__ out) {
    const int b   = blockIdx.x;
    const int tid = threadIdx.x;

    if (b < 2048) {
        int r  = 1 + (b >> 1);
        int c0 = ((b & 1) << 10) + tid;
        const float4* xs = (const float4*)(x + (size_t)r * F);
        const float4* sc = (const float4*)g_scale;
        float4* os = (float4*)(out + (size_t)r * F);
        #pragma unroll
        for (int j = 0; j < 4; ++j) {
            int i = c0 + (j << 8);
            float4 v = xs[i];
            float4 s = sc[i];
            float4 o;
            o.x = s.x * v.x;
            o.y = s.y * v.y;
            o.z = s.z * v.z;
            o.w = s.w * v.w;
            __stcs(&os[i], o);             // out never re-read: bypass L2 fill
        }
    } else {
        int e     = b - 2048;
        int row   = e >> 1;
        int diag4 = row >> 2;              // float4 slot owned by finalize
        int c0    = ((e & 1) << 10) + tid;
        float4* os = (float4*)(out + (size_t)(KROWS + row) * F);
        const float4 z = make_float4(0.f, 0.f, 0.f, 0.f);
        #pragma unroll
        for (int j = 0; j < 4; ++j) {
            int i = c0 + (j << 8);
            if (i != diag4) __stcs(&os[i], z);
        }
    }
}

extern "C" void kernel_launch(void* const* d_in, const int* in_sizes, int n_in,
                              void* d_out, int out_size) {
    const float* x       = (const float*)d_in[0];
    const float* lambdas = (const float*)d_in[1];
    float* out           = (float*)d_out;

    // 1) Partial abs-sums
    {
        dim3 grid(F / 4 / 256, NCHUNK);    // 8 x 128
        relu_z_partial_abs<<<grid, 256>>>(x);
    }
    // 2) Finalize: scale, center row, ext diagonal
    relu_z_finalize<<<F / 256, 256>>>(x, lambdas, out);
    // 3) Everything else: body rows + ext zeros, one launch
    relu_z_store_all<<<2048 + 16384, 256>>>(x, out);
}

// round 16
// speedup vs baseline: 1.0358x; 1.0069x over previous
#include <cuda_runtime.h>

// Problem constants (fixed shapes per reference)
#define KROWS 1025
#define F     8192
#define NCHUNK 128
#define ROWS_PER_CHUNK 8   // 1024/128

// Device scratch (no allocations in kernel_launch)
__device__ float g_partial[NCHUNK * F];   // 4 MB
__device__ float g_scale[F];

// Kernel 1: partial column-wise sum of |x| over rows 1..1024.
// 8 col-blocks x 128 row-chunks = 1024 blocks (proven optimum config).
__global__ void relu_z_partial_abs(const float* __restrict__ x) {
    int c4    = blockIdx.x * blockDim.x + threadIdx.x;  // 0..F/4-1
    int chunk = blockIdx.y;                             // 0..127
    int r0 = 1 + chunk * ROWS_PER_CHUNK;

    const float4* p = (const float4*)(x + (size_t)r0 * F) + c4;
    float4 s = make_float4(0.f, 0.f, 0.f, 0.f);
    #pragma unroll
    for (int r = 0; r < ROWS_PER_CHUNK; ++r) {
        float4 v = p[(size_t)r * (F / 4)];
        s.x += fabsf(v.x);
        s.y += fabsf(v.y);
        s.z += fabsf(v.z);
        s.w += fabsf(v.w);
    }
    ((float4*)(g_partial + chunk * F))[c4] = s;
}

// Kernel 2: fold partials -> scale; write center row + ext diagonal float4.
// PDL: triggers its successor at entry (store_all ext blocks have no
// dependency on us), then waits for partial_abs before reading g_partial.
__global__ void relu_z_finalize(const float* __restrict__ x,
                                const float* __restrict__ lambdas,
                                float* __restrict__ out) {
    cudaTriggerProgrammaticLaunchCompletion();   // let store_all launch now
    cudaGridDependencySynchronize();             // wait: g_partial complete

    int f = blockIdx.x * blockDim.x + threadIdx.x;
    float abssum = 0.0f;
    #pragma unroll 16
    for (int c = 0; c < NCHUNK; ++c) abssum += g_partial[c * F + f];

    float ctr = x[f];                 // x[0][f]
    float l = ctr - abssum;
    float u = ctr + abssum;
    float lam = lambdas[f];

    float pos   = (l > 0.0f) ? 1.0f : 0.0f;
    float cross = ((u > 0.0f) && (l < 0.0f)) ? 1.0f : 0.0f;
    float d     = fmaxf(-l * lam, u * (1.0f - lam));
    float scale = pos + cross * lam;
    float half  = 0.5f * cross * d;

    g_scale[f] = scale;
    out[f] = scale * ctr + half;      // center row

    // diagonal float4 of the ext block (store_all skips this slot)
    float4 dv = make_float4(0.f, 0.f, 0.f, 0.f);
    ((float*)&dv)[f & 3] = half;
    ((float4*)(out + (size_t)(KROWS + f) * F))[f >> 2] = dv;
}

// Kernel 3: ALL remaining stores. PDL-launched: ext blocks start immediately
// (their bytes are disjoint from finalize's writes); body blocks sync on
// finalize before reading g_scale.
__global__ void __launch_bounds__(256) relu_z_store_all(
    const float* __restrict__ x, float* __restrict__ out) {
    const int b   = blockIdx.x;
    const int tid = threadIdx.x;

    if (b < 2048) {
        cudaGridDependencySynchronize();   // need g_scale from finalize
        int r  = 1 + (b >> 1);
        int c0 = ((b & 1) << 10) + tid;
        const float4* xs = (const float4*)(x + (size_t)r * F);
        const float4* sc = (const float4*)g_scale;
        float4* os = (float4*)(out + (size_t)r * F);
        #pragma unroll
        for (int j = 0; j < 4; ++j) {
            int i = c0 + (j << 8);
            float4 v = xs[i];
            float4 s = sc[i];
            float4 o;
            o.x = s.x * v.x;
            o.y = s.y * v.y;
            o.z = s.z * v.z;
            o.w = s.w * v.w;
            __stcs(&os[i], o);             // out never re-read: bypass L2 fill
        }
    } else {
        // No dependency: zeros are disjoint from finalize's diagonal float4s.
        int e     = b - 2048;
        int row   = e >> 1;
        int diag4 = row >> 2;              // float4 slot owned by finalize
        int c0    = ((e & 1) << 10) + tid;
        float4* os = (float4*)(out + (size_t)(KROWS + row) * F);
        const float4 z = make_float4(0.f, 0.f, 0.f, 0.f);
        #pragma unroll
        for (int j = 0; j < 4; ++j) {
            int i = c0 + (j << 8);
            if (i != diag4) __stcs(&os[i], z);
        }
    }
}

extern "C" void kernel_launch(void* const* d_in, const int* in_sizes, int n_in,
                              void* d_out, int out_size) {
    const float* x       = (const float*)d_in[0];
    const float* lambdas = (const float*)d_in[1];
    float* out           = (float*)d_out;

    // 1) Partial abs-sums (plain launch; implicit PDL trigger at kernel end)
    {
        dim3 grid(F / 4 / 256, NCHUNK);    // 8 x 128
        relu_z_partial_abs<<<grid, 256>>>(x);
    }

    // PDL attribute: allow programmatic (early) launch w.r.t. predecessor.
    cudaLaunchAttribute attr[1];
    attr[0].id = cudaLaunchAttributeProgrammaticStreamSerialization;
    attr[0].val.programmaticStreamSerializationAllowed = 1;

    // 2) Finalize — overlaps partial_abs's launch tail, syncs internally.
    {
        cudaLaunchConfig_t cfg = {};
        cfg.gridDim  = dim3(F / 256);
        cfg.blockDim = dim3(256);
        cfg.stream   = 0;
        cfg.attrs    = attr;
        cfg.numAttrs = 1;
        cudaLaunchKernelEx(&cfg, relu_z_finalize, x, lambdas, out);
    }

    // 3) store_all — ext blocks launch as soon as finalize triggers (entry);
    //    body blocks sync on finalize completion internally.
    {
        cudaLaunchConfig_t cfg = {};
        cfg.gridDim  = dim3(2048 + 16384);
        cfg.blockDim = dim3(256);
        cfg.stream   = 0;
        cfg.attrs    = attr;
        cfg.numAttrs = 1;
        cudaLaunchKernelEx(&cfg, relu_z_store_all, x, out);
    }
}

// round 17
// speedup vs baseline: 1.0364x; 1.0006x over previous
#include <cuda_runtime.h>

// Problem constants (fixed shapes per reference)
#define KROWS 1025
#define F     8192
#define NCHUNK 128
#define ROWS_PER_CHUNK 8   // 1024/128

// Device scratch (no allocations in kernel_launch)
__device__ float g_partial[NCHUNK * F];   // 4 MB
__device__ float g_scale[F];

// Kernel 1: partial column-wise sum of |x| over rows 1..1024.
// __launch_bounds__(256, 2): raise the register ceiling so ptxas can keep all
// 8 LDG.128 results live simultaneously (31-reg variants serialize the loads).
__global__ void __launch_bounds__(256, 2) relu_z_partial_abs(
    const float* __restrict__ x)
{
    const int c4    = blockIdx.x * blockDim.x + threadIdx.x;  // 0..F/4-1
    const int chunk = blockIdx.y;                             // 0..127
    const size_t st = F / 4;

    const float4* p =
        (const float4*)(x + (size_t)(1 + chunk * ROWS_PER_CHUNK) * F) + c4;

    float4 v0 = p[0 * st];
    float4 v1 = p[1 * st];
    float4 v2 = p[2 * st];
    float4 v3 = p[3 * st];
    float4 v4 = p[4 * st];
    float4 v5 = p[5 * st];
    float4 v6 = p[6 * st];
    float4 v7 = p[7 * st];

    float4 a, b;
    a.x = (fabsf(v0.x) + fabsf(v1.x)) + (fabsf(v2.x) + fabsf(v3.x));
    a.y = (fabsf(v0.y) + fabsf(v1.y)) + (fabsf(v2.y) + fabsf(v3.y));
    a.z = (fabsf(v0.z) + fabsf(v1.z)) + (fabsf(v2.z) + fabsf(v3.z));
    a.w = (fabsf(v0.w) + fabsf(v1.w)) + (fabsf(v2.w) + fabsf(v3.w));
    b.x = (fabsf(v4.x) + fabsf(v5.x)) + (fabsf(v6.x) + fabsf(v7.x));
    b.y = (fabsf(v4.y) + fabsf(v5.y)) + (fabsf(v6.y) + fabsf(v7.y));
    b.z = (fabsf(v4.z) + fabsf(v5.z)) + (fabsf(v6.z) + fabsf(v7.z));
    b.w = (fabsf(v4.w) + fabsf(v5.w)) + (fabsf(v6.w) + fabsf(v7.w));

    float4 s;
    s.x = a.x + b.x; s.y = a.y + b.y; s.z = a.z + b.z; s.w = a.w + b.w;
    ((float4*)(g_partial + chunk * F))[c4] = s;
}

// Kernel 2: fold partials -> scale; write center row + ext diagonal float4.
// PDL: triggers successor at entry, then waits for partial_abs.
__global__ void relu_z_finalize(const float* __restrict__ x,
                                const float* __restrict__ lambdas,
                                float* __restrict__ out) {
    cudaTriggerProgrammaticLaunchCompletion();   // let store_all launch now
    cudaGridDependencySynchronize();             // wait: g_partial complete

    int f = blockIdx.x * blockDim.x + threadIdx.x;
    float abssum = 0.0f;
    #pragma unroll 16
    for (int c = 0; c < NCHUNK; ++c) abssum += g_partial[c * F + f];

    float ctr = x[f];                 // x[0][f]
    float l = ctr - abssum;
    float u = ctr + abssum;
    float lam = lambdas[f];

    float pos   = (l > 0.0f) ? 1.0f : 0.0f;
    float cross = ((u > 0.0f) && (l < 0.0f)) ? 1.0f : 0.0f;
    float d     = fmaxf(-l * lam, u * (1.0f - lam));
    float scale = pos + cross * lam;
    float half  = 0.5f * cross * d;

    g_scale[f] = scale;
    out[f] = scale * ctr + half;      // center row

    // diagonal float4 of the ext block (store_all skips this slot)
    float4 dv = make_float4(0.f, 0.f, 0.f, 0.f);
    ((float*)&dv)[f & 3] = half;
    ((float4*)(out + (size_t)(KROWS + f) * F))[f >> 2] = dv;
}

// Kernel 3: ALL remaining stores. PDL-launched: ext blocks start immediately
// (bytes disjoint from finalize); body blocks sync on finalize for g_scale.
__global__ void __launch_bounds__(256) relu_z_store_all(
    const float* __restrict__ x, float* __restrict__ out) {
    const int b   = blockIdx.x;
    const int tid = threadIdx.x;

    if (b < 2048) {
        cudaGridDependencySynchronize();   // need g_scale from finalize
        int r  = 1 + (b >> 1);
        int c0 = ((b & 1) << 10) + tid;
        const float4* xs = (const float4*)(x + (size_t)r * F);
        const float4* sc = (const float4*)g_scale;
        float4* os = (float4*)(out + (size_t)r * F);
        #pragma unroll
        for (int j = 0; j < 4; ++j) {
            int i = c0 + (j << 8);
            float4 v = xs[i];
            float4 s = sc[i];
            float4 o;
            o.x = s.x * v.x;
            o.y = s.y * v.y;
            o.z = s.z * v.z;
            o.w = s.w * v.w;
            __stcs(&os[i], o);             // out never re-read: bypass L2 fill
        }
    } else {
        int e     = b - 2048;
        int row   = e >> 1;
        int diag4 = row >> 2;              // float4 slot owned by finalize
        int c0    = ((e & 1) << 10) + tid;
        float4* os = (float4*)(out + (size_t)(KROWS + row) * F);
        const float4 z = make_float4(0.f, 0.f, 0.f, 0.f);
        #pragma unroll
        for (int j = 0; j < 4; ++j) {
            int i = c0 + (j << 8);
            if (i != diag4) __stcs(&os[i], z);
        }
    }
}

extern "C" void kernel_launch(void* const* d_in, const int* in_sizes, int n_in,
                              void* d_out, int out_size) {
    const float* x       = (const float*)d_in[0];
    const float* lambdas = (const float*)d_in[1];
    float* out           = (float*)d_out;

    // 1) Partial abs-sums
    {
        dim3 grid(F / 4 / 256, NCHUNK);    // 8 x 128
        relu_z_partial_abs<<<grid, 256>>>(x);
    }

    cudaLaunchAttribute attr[1];
    attr[0].id = cudaLaunchAttributeProgrammaticStreamSerialization;
    attr[0].val.programmaticStreamSerializationAllowed = 1;

    // 2) Finalize — overlaps partial_abs's tail, syncs internally (PDL).
    {
        cudaLaunchConfig_t cfg = {};
        cfg.gridDim  = dim3(F / 256);
        cfg.blockDim = dim3(256);
        cfg.stream   = 0;
        cfg.attrs    = attr;
        cfg.numAttrs = 1;
        cudaLaunchKernelEx(&cfg, relu_z_finalize, x, lambdas, out);
    }

    // 3) store_all — ext blocks launch at finalize's entry trigger (PDL).
    {
        cudaLaunchConfig_t cfg = {};
        cfg.gridDim  = dim3(2048 + 16384);
        cfg.blockDim = dim3(256);
        cfg.stream   = 0;
        cfg.attrs    = attr;
        cfg.numAttrs = 1;
        cudaLaunchKernelEx(&cfg, relu_z_store_all, x, out);
    }
}